// round 8
// baseline (speedup 1.0000x reference)
#include <cuda_runtime.h>
#include <cstdint>

// CTC loss, probability-domain forward DP, per-lane block-float exponents.
// R8 = R7 + software-pipelined prob gather: chunk c+1's 24 LDS gathers issue
// in parallel with chunk c's FMA/shfl DP chain, removing LDS latency and
// bank-conflict serialization from the per-chunk critical path.
// B=512, T=512, C=128, L=64, S=129, blank=127. One warp per batch element.

#define CTC_B 512
#define CTC_T 512
#define CTC_C 128
#define CTC_L 64
#define CH    8                 // rows (time steps) per chunk = rescale period
#define RCH   12                // ring slots (48 KB smem)
#define LA    (RCH - 1)         // lookahead chunks committed ahead (11)
#define NCH   (CTC_T / CH)      // 64 chunks

__global__ __launch_bounds__(32) void ctc_kernel(
    const int* __restrict__ y_true,
    const float* __restrict__ y_pred,
    float* __restrict__ out)
{
    __shared__ float ring[RCH * CH * CTC_C];   // 48 KB

    const float EPS = 1e-7f;
    const unsigned FULL = 0xffffffffu;
    const int b    = blockIdx.x;
    const int lane = threadIdx.x;

    // labels for odd states s=4l+1 (label 2l) and s=4l+3 (label 2l+1)
    const int* lrow = y_true + b * CTC_L;
    const int lab1 = lrow[2 * lane];
    const int lab3 = lrow[2 * lane + 1];
    const int prev1 = (lane > 0) ? lrow[2 * lane - 1] : -1;
    const bool allow1 = (lane > 0) && (lab1 != prev1);
    const bool allow3 = (lab3 != lab1);

    const float* base = y_pred + (size_t)b * CTC_T * CTC_C;
    const unsigned smb = (unsigned)__cvta_generic_to_shared(ring);
    const unsigned lane4 = 4u * lane;

    auto issue_chunk = [&](int c, int slot) {
        const unsigned sbase = (unsigned)slot * (CH * CTC_C);
#pragma unroll
        for (int r = 0; r < CH; ++r) {
            const float* src = base + (size_t)(c * CH + r) * CTC_C + lane4;
            const unsigned dst = smb + (sbase + (unsigned)r * CTC_C + lane4) * 4u;
            asm volatile("cp.async.cg.shared.global [%0], [%1], 16;"
                         :: "r"(dst), "l"(src));
        }
        asm volatile("cp.async.commit_group;");
    };

    // Prologue: fill LA chunks (slots 0..LA-1), then gather chunk 0's probs.
#pragma unroll
    for (int c = 0; c < LA; ++c) issue_chunk(c, c);

    asm volatile("cp.async.wait_group %0;" :: "n"(LA - 1));  // chunk 0 complete
    __syncwarp();

    float pbc[CH], p1c[CH], p3c[CH];     // current-chunk probs (registers)
#pragma unroll
    for (int j = 0; j < CH; ++j) {
        const int rb = j * CTC_C;
        pbc[j] = ring[rb + (CTC_C - 1)] + EPS;
        p1c[j] = ring[rb + lab1] + EPS;
        p3c[j] = ring[rb + lab3] + EPS;
    }

    // virtual pre-init: a0=1 on lane 0 makes step t=0 yield the reference init
    float a0 = (lane == 0) ? 1.0f : 0.0f;
    float a1 = 0.0f, a2 = 0.0f, a3 = 0.0f, a4 = 0.0f;
    int   E  = 0;                               // alpha = a * 2^E (per lane)
    float f  = (lane == 0) ? 0.0f : 1.0f;       // neighbor re-basing factor

    int nslot = 1;       // slot holding chunk c+1 (gather target)
    int wslot = LA;      // slot for chunk c+LA (reads finished in iter c-2)

    for (int c = 0; c < NCH; ++c) {
        if (c + LA < NCH) issue_chunk(c + LA, wslot);
        else asm volatile("cp.async.commit_group;");   // uniform group accounting

        // committed = c + LA + 1; pending <= LA-1 -> chunks 0..c+1 complete
        asm volatile("cp.async.wait_group %0;" :: "n"(LA - 1));
        __syncwarp();

        // Gather chunk c+1's probs (independent LDS stream — overlaps the DP
        // chain below in the scheduler).
        float pbn[CH], p1n[CH], p3n[CH];
        if (c + 1 < NCH) {
            const int nb = nslot * (CH * CTC_C);
#pragma unroll
            for (int j = 0; j < CH; ++j) {
                const int rb = nb + j * CTC_C;
                pbn[j] = ring[rb + (CTC_C - 1)] + EPS;
                p1n[j] = ring[rb + lab1] + EPS;
                p3n[j] = ring[rb + lab3] + EPS;
            }
        } else {
#pragma unroll
            for (int j = 0; j < CH; ++j) { pbn[j] = p1n[j] = p3n[j] = 0.0f; }
        }

        // 8 DP steps (pure FADD/FMUL + 1 shfl each) on current-chunk regs.
#pragma unroll
        for (int j = 0; j < CH; ++j) {
            const float am1 = __shfl_up_sync(FULL, a3, 1) * f;   // lane0: f=0

            const float n0 = (a0 + am1) * pbc[j];                          // s=4l (blank)
            const float n1 = (a1 + a0 + (allow1 ? am1 : 0.0f)) * p1c[j];   // s=4l+1
            const float n2 = (a2 + a1) * pbc[j];                           // s=4l+2
            const float n3 = (a3 + a2 + (allow3 ? a1 : 0.0f)) * p3c[j];    // s=4l+3
            const float n4 = (a4 + a3) * pbc[j];                           // s=128 (lane31)
            a0 = n0; a1 = n1; a2 = n2; a3 = n3; a4 = n4;
        }

        // ---- per-lane power-of-2 rescale (every 8 steps) ----
        {
            float lm = fmaxf(fmaxf(a0, a1), fmaxf(a2, a3));
            lm = fmaxf(lm, a4);
            int e = (int)(__float_as_uint(lm) >> 23) - 127;
            const bool zero = (lm == 0.0f);
            if (zero) e = 0;
            const float sc = __uint_as_float((unsigned)(127 - e) << 23); // 2^-e
            a0 *= sc; a1 *= sc; a2 *= sc; a3 *= sc; a4 *= sc;
            E += e;
            const int Ep = __shfl_up_sync(FULL, E, 1);
            if (zero && lane > 0) E = Ep;      // adopt neighbor frame ahead of wavefront
            const int Ep2 = __shfl_up_sync(FULL, E, 1);
            int d = Ep2 - E;
            d = max(-126, min(126, d));
            f = __uint_as_float((unsigned)(127 + d) << 23);  // 2^d
            if (lane == 0) f = 0.0f;
        }

        // rotate prob registers and ring slots
#pragma unroll
        for (int j = 0; j < CH; ++j) { pbc[j] = pbn[j]; p1c[j] = p1n[j]; p3c[j] = p3n[j]; }
        nslot = (nslot + 1 == RCH) ? 0 : nslot + 1;
        wslot = (wslot + 1 == RCH) ? 0 : wslot + 1;
    }

    if (lane == 31) {
        // P_total = alpha_{T-1}[S-1] + alpha_{T-1}[S-2] = (a4 + a3) * 2^E
        const float p = a4 + a3;
        out[b] = -(__logf(p) + (float)E * 0.69314718055994530942f);
    }
}

extern "C" void kernel_launch(void* const* d_in, const int* in_sizes, int n_in,
                              void* d_out, int out_size) {
    const int*   y_true = (const int*)d_in[0];
    const float* y_pred = (const float*)d_in[1];
    float*       outp   = (float*)d_out;
    (void)in_sizes; (void)n_in; (void)out_size;

    ctc_kernel<<<CTC_B, 32>>>(y_true, y_pred, outp);
}

// round 9
// speedup vs baseline: 1.1521x; 1.1521x over previous
#include <cuda_runtime.h>
#include <cstdint>

// CTC loss, probability-domain forward DP, per-lane block-float exponents.
// R9: ping-pong gather overlap. Main loop unrolled x2 with two alternating
// prob-register sets (A/B): while the DP chain of chunk c runs on set A, the
// 24 LDS gathers of chunk c+1 fill set B (and vice versa). No register
// rotation MOVs (the R8 mistake), no extra work on the critical chain.
// B=512, T=512, C=128, L=64, S=129, blank=127. One warp per batch element.

#define CTC_B 512
#define CTC_T 512
#define CTC_C 128
#define CTC_L 64
#define CH    8                 // rows per chunk = rescale period
#define RCH   12                // ring slots (48 KB smem)
#define LA    (RCH - 1)         // lookahead chunks committed ahead (11)
#define NCH   (CTC_T / CH)      // 64 chunks (even -> clean x2 unroll)

__global__ __launch_bounds__(32) void ctc_kernel(
    const int* __restrict__ y_true,
    const float* __restrict__ y_pred,
    float* __restrict__ out)
{
    __shared__ float ring[RCH * CH * CTC_C];   // 48 KB

    const float EPS = 1e-7f;
    const unsigned FULL = 0xffffffffu;
    const int b    = blockIdx.x;
    const int lane = threadIdx.x;

    const int* lrow = y_true + b * CTC_L;
    const int lab1 = lrow[2 * lane];
    const int lab3 = lrow[2 * lane + 1];
    const int prev1 = (lane > 0) ? lrow[2 * lane - 1] : -1;
    const bool allow1 = (lane > 0) && (lab1 != prev1);
    const bool allow3 = (lab3 != lab1);

    const float* base = y_pred + (size_t)b * CTC_T * CTC_C;
    const unsigned smb = (unsigned)__cvta_generic_to_shared(ring);
    const unsigned lane4 = 4u * lane;

    auto issue_chunk = [&](int c, int slot) {
        const unsigned sbase = (unsigned)slot * (CH * CTC_C);
#pragma unroll
        for (int r = 0; r < CH; ++r) {
            const float* src = base + (size_t)(c * CH + r) * CTC_C + lane4;
            const unsigned dst = smb + (sbase + (unsigned)r * CTC_C + lane4) * 4u;
            asm volatile("cp.async.cg.shared.global [%0], [%1], 16;"
                         :: "r"(dst), "l"(src));
        }
        asm volatile("cp.async.commit_group;");
    };

    // Prologue: fill LA chunks, then gather chunk 0 into set A.
#pragma unroll
    for (int c = 0; c < LA; ++c) issue_chunk(c, c);
    asm volatile("cp.async.wait_group %0;" :: "n"(LA - 1));
    __syncwarp();

    float pbA[CH], p1A[CH], p3A[CH];
    float pbB[CH], p1B[CH], p3B[CH];
#pragma unroll
    for (int j = 0; j < CH; ++j) {
        const int rb = j * CTC_C;
        pbA[j] = ring[rb + (CTC_C - 1)] + EPS;
        p1A[j] = ring[rb + lab1] + EPS;
        p3A[j] = ring[rb + lab3] + EPS;
    }

    float a0 = (lane == 0) ? 1.0f : 0.0f;   // virtual pre-init (yields ref t=0)
    float a1 = 0.0f, a2 = 0.0f, a3 = 0.0f, a4 = 0.0f;
    int   E  = 0;                            // alpha = a * 2^E (per lane)
    float f  = (lane == 0) ? 0.0f : 1.0f;    // neighbor re-basing factor

    int nslot = 1;    // slot of chunk c+1 (gather target)
    int wslot = LA;   // slot for chunk c+LA

#define GATHER(SET_PB, SET_P1, SET_P3, C1)                                 \
    do {                                                                    \
        if ((C1) < NCH) {                                                   \
            const int nb_ = nslot * (CH * CTC_C);                           \
            _Pragma("unroll")                                               \
            for (int j = 0; j < CH; ++j) {                                  \
                const int rb_ = nb_ + j * CTC_C;                            \
                SET_PB[j] = ring[rb_ + (CTC_C - 1)] + EPS;                  \
                SET_P1[j] = ring[rb_ + lab1] + EPS;                         \
                SET_P3[j] = ring[rb_ + lab3] + EPS;                         \
            }                                                               \
        }                                                                   \
    } while (0)

#define DPCHUNK(PB, P1, P3)                                                \
    do {                                                                    \
        _Pragma("unroll")                                                   \
        for (int j = 0; j < CH; ++j) {                                      \
            const float am1 = __shfl_up_sync(FULL, a3, 1) * f;              \
            const float n0 = (a0 + am1) * PB[j];                            \
            const float n1 = (a1 + a0 + (allow1 ? am1 : 0.0f)) * P1[j];     \
            const float n2 = (a2 + a1) * PB[j];                             \
            const float n3 = (a3 + a2 + (allow3 ? a1 : 0.0f)) * P3[j];      \
            const float n4 = (a4 + a3) * PB[j];                             \
            a0 = n0; a1 = n1; a2 = n2; a3 = n3; a4 = n4;                    \
        }                                                                   \
        /* per-lane power-of-2 rescale */                                   \
        {                                                                   \
            float lm = fmaxf(fmaxf(a0, a1), fmaxf(a2, a3));                 \
            lm = fmaxf(lm, a4);                                             \
            int e = (int)(__float_as_uint(lm) >> 23) - 127;                 \
            const bool zero = (lm == 0.0f);                                 \
            if (zero) e = 0;                                                \
            const float sc = __uint_as_float((unsigned)(127 - e) << 23);    \
            a0 *= sc; a1 *= sc; a2 *= sc; a3 *= sc; a4 *= sc;               \
            E += e;                                                         \
            const int Ep = __shfl_up_sync(FULL, E, 1);                      \
            if (zero && lane > 0) E = Ep;                                   \
            const int Ep2 = __shfl_up_sync(FULL, E, 1);                     \
            int d = Ep2 - E;                                                \
            d = max(-126, min(126, d));                                     \
            f = __uint_as_float((unsigned)(127 + d) << 23);                 \
            if (lane == 0) f = 0.0f;                                        \
        }                                                                   \
    } while (0)

#define ADVANCE()                                                           \
    do {                                                                    \
        nslot = (nslot + 1 == RCH) ? 0 : nslot + 1;                         \
        wslot = (wslot + 1 == RCH) ? 0 : wslot + 1;                         \
    } while (0)

    for (int c = 0; c < NCH; c += 2) {
        // ---- even body: DP on set A, gather c+1 into set B ----
        if (c + LA < NCH) issue_chunk(c + LA, wslot);
        else asm volatile("cp.async.commit_group;");
        asm volatile("cp.async.wait_group %0;" :: "n"(LA - 1));  // c+1 resident
        __syncwarp();

        GATHER(pbB, p1B, p3B, c + 1);
        DPCHUNK(pbA, p1A, p3A);
        ADVANCE();

        // ---- odd body: DP on set B, gather c+2 into set A ----
        if (c + 1 + LA < NCH) issue_chunk(c + 1 + LA, wslot);
        else asm volatile("cp.async.commit_group;");
        asm volatile("cp.async.wait_group %0;" :: "n"(LA - 1));  // c+2 resident
        __syncwarp();

        GATHER(pbA, p1A, p3A, c + 2);
        DPCHUNK(pbB, p1B, p3B);
        ADVANCE();
    }

#undef GATHER
#undef DPCHUNK
#undef ADVANCE

    if (lane == 31) {
        // P_total = alpha_{T-1}[S-1] + alpha_{T-1}[S-2] = (a4 + a3) * 2^E
        const float p = a4 + a3;
        out[b] = -(__logf(p) + (float)E * 0.69314718055994530942f);
    }
}

extern "C" void kernel_launch(void* const* d_in, const int* in_sizes, int n_in,
                              void* d_out, int out_size) {
    const int*   y_true = (const int*)d_in[0];
    const float* y_pred = (const float*)d_in[1];
    float*       outp   = (float*)d_out;
    (void)in_sizes; (void)n_in; (void)out_size;

    ctc_kernel<<<CTC_B, 32>>>(y_true, y_pred, outp);
}